// round 11
// baseline (speedup 1.0000x reference)
#include <cuda_runtime.h>
#include <cuda_fp16.h>

#define DINL __device__ __forceinline__

// ---------------- problem constants ----------------
constexpr int Bn = 4096;
constexpr int In = 512;
constexpr int Hn = 1024;
constexpr int Kd = Hn + In;      // 1536
constexpr int Nt = 8 * Hn;       // 8192 packed gate columns

// ---------------- GEMM tiling ----------------
// Fused kernel, 2 CTAs/SM: BM=128 rows x BN=128 packed cols (16 j x 8 gate/branch).
// 4 warps (128 thr), warp tile 64x64: wm in {0,1}, wn in {0,1}.
// wn 0 -> A_light (cols 0..63 = gb 0..3), wn 1 -> A_temp (cols 64..127).
constexpr int BM = 128;
constexpr int BN = 128;
constexpr int JT = 16;                              // j-values per CTA
constexpr int BK = 64;                              // 128 bytes fp16 per row
constexpr int NK = Kd / BK;                         // 24
constexpr int STAGES = 2;
constexpr int STAGE_AL = BM * BK * 2;               // 16384
constexpr int STAGE_AT = BM * BK * 2;               // 16384
constexpr int STAGE_B  = BN * BK * 2;               // 16384
constexpr int STAGE_BYTES = STAGE_AL + STAGE_AT + STAGE_B;   // 49152
constexpr int SMEM_TOTAL = STAGES * STAGE_BYTES;    // 98304 per CTA (2 CTAs fit)
// epilogue transpose: 128 x 136 fp32 = 69632 B, reuses the same smem. fits.
constexpr int EPAD = 136;

// ---------------- scratch (device globals; no allocations) ----------------
__device__ __align__(1024) __half g_A[2][(long)Bn * Kd];          // 25 MB
__device__ __align__(1024) __half g_W[(long)Nt * Kd];             // 25 MB (packed)

// ---------------- PTX helpers (legal on plain sm_103 target) ----------
DINL unsigned cvta_smem(const void* p) {
    unsigned a;
    asm("{ .reg .u64 t; cvta.to.shared.u64 t, %1; cvt.u32.u64 %0, t; }" : "=r"(a) : "l"(p));
    return a;
}
DINL void cp_async16(unsigned dst, const void* src) {
    asm volatile("cp.async.cg.shared.global [%0], [%1], 16;" :: "r"(dst), "l"(src));
}
DINL void ldsm_x4(unsigned& r0, unsigned& r1, unsigned& r2, unsigned& r3, unsigned addr) {
    asm volatile("ldmatrix.sync.aligned.m8n8.x4.shared.b16 {%0,%1,%2,%3}, [%4];"
                 : "=r"(r0), "=r"(r1), "=r"(r2), "=r"(r3) : "r"(addr));
}
DINL void mma16816(float& d0, float& d1, float& d2, float& d3,
                   unsigned a0, unsigned a1, unsigned a2, unsigned a3,
                   unsigned b0, unsigned b1) {
    asm volatile(
        "mma.sync.aligned.m16n8k16.row.col.f32.f16.f16.f32 "
        "{%0,%1,%2,%3}, {%4,%5,%6,%7}, {%8,%9}, {%0,%1,%2,%3};"
        : "+f"(d0), "+f"(d1), "+f"(d2), "+f"(d3)
        : "r"(a0), "r"(a1), "r"(a2), "r"(a3), "r"(b0), "r"(b1));
}
DINL float htanh(float x) {
    float r;
    asm("tanh.approx.f32 %0, %1;" : "=f"(r) : "f"(x));
    return r;
}
DINL float sigf(float x) { return fmaf(htanh(x * 0.5f), 0.5f, 0.5f); }

// ---------------- convert kernel (one row per block, no div/mod) ----------
// grid (4096, 4), 192 threads. y=0/1: A branches. y=2/3: packed W rows
// n = (y-2)*4096 + x with jt=n>>7, gb=(n>>4)&7, jj=n&15, src row j=jt*16+jj.
__global__ void __launch_bounds__(192) convert_all(
        const float* __restrict__ y,
        const float* __restrict__ hl,
        const float* __restrict__ ht,
        const float* __restrict__ w0, const float* __restrict__ w1,
        const float* __restrict__ w2, const float* __restrict__ w3,
        const float* __restrict__ w4, const float* __restrict__ w5,
        const float* __restrict__ w6, const float* __restrict__ w7) {
    const int t  = threadIdx.x;
    const int bx = blockIdx.x;
    const int by = blockIdx.y;
    const float* src;
    __half* dst;
    if (by < 2) {
        const float* hsrc = by ? ht : hl;
        src = (t < 128) ? hsrc + (long)bx * Hn + t * 8
                        : y + (long)bx * In + (t - 128) * 8;
        dst = &g_A[by][(long)bx * Kd + t * 8];
    } else {
        const int n  = (by - 2) * 4096 + bx;
        const int jt = n >> 7;
        const int gb = (n >> 4) & 7;
        const int jj = n & 15;
        const int j  = jt * JT + jj;
        const float* wp = (gb == 0) ? w0 : (gb == 1) ? w1 : (gb == 2) ? w2 : (gb == 3) ? w3
                        : (gb == 4) ? w4 : (gb == 5) ? w5 : (gb == 6) ? w6 : w7;
        src = wp + (long)j * Kd + t * 8;
        dst = &g_W[(long)n * Kd + t * 8];
    }
    float4 a = reinterpret_cast<const float4*>(src)[0];
    float4 b = reinterpret_cast<const float4*>(src)[1];
    __half2 h0 = __floats2half2_rn(a.x, a.y);
    __half2 h1 = __floats2half2_rn(a.z, a.w);
    __half2 h2 = __floats2half2_rn(b.x, b.y);
    __half2 h3 = __floats2half2_rn(b.z, b.w);
    uint4 v = make_uint4(*(unsigned*)&h0, *(unsigned*)&h1,
                         *(unsigned*)&h2, *(unsigned*)&h3);
    *reinterpret_cast<uint4*>(dst) = v;
}

// ---------------- fused GEMM + LSTM kernel ----------------
// 48KB stage: A_l (128x128B) + A_t + B, 128 threads, 8 iters of 16 rows/section.
DINL void load_stage(unsigned sbase, unsigned soff,
                     const __half* pAl, const __half* pAt, const __half* pB) {
#pragma unroll
    for (int i = 0; i < 8; i++)
        cp_async16(sbase + i * 2048 + soff, pAl + (long)i * 16 * Kd);
#pragma unroll
    for (int i = 0; i < 8; i++)
        cp_async16(sbase + STAGE_AL + i * 2048 + soff, pAt + (long)i * 16 * Kd);
#pragma unroll
    for (int i = 0; i < 8; i++)
        cp_async16(sbase + STAGE_AL + STAGE_AT + i * 2048 + soff, pB + (long)i * 16 * Kd);
    asm volatile("cp.async.commit_group;" ::: "memory");
}

__global__ void __launch_bounds__(128, 2) gemm_lstm(
        const float* __restrict__ cl,
        const float* __restrict__ b0, const float* __restrict__ b1,
        const float* __restrict__ b2, const float* __restrict__ b3,
        const float* __restrict__ b4, const float* __restrict__ b5,
        const float* __restrict__ b6, const float* __restrict__ b7,
        float* __restrict__ out) {
    extern __shared__ char smem[];
    const unsigned tid  = threadIdx.x;
    const unsigned wid  = tid >> 5;
    const unsigned lane = tid & 31;
    const unsigned sb   = cvta_smem(smem);
    const unsigned wm   = wid & 1;        // 2 warps along M -> 64 rows each
    const unsigned wn   = wid >> 1;       // 2 warps along N -> 64 cols each
    const int n0 = blockIdx.x * BN;       // packed col base
    const int m0 = blockIdx.y * BM;
    const int j0 = blockIdx.x * JT;

    // per-thread cp.async bases (affine; swizzle term constant since 16 % 8 == 0)
    const unsigned trow = tid >> 3;                 // 0..15
    const unsigned tcol = tid & 7;
    const __half* pAl = g_A[0] + (long)(m0 + trow) * Kd + tcol * 8;
    const __half* pAt = g_A[1] + (long)(m0 + trow) * Kd + tcol * 8;
    const __half* pB  = g_W   + (long)(n0 + trow) * Kd + tcol * 8;
    const unsigned soff = trow * 128 + ((tcol * 16) ^ ((trow & 7) << 4));

    // prologue loads (stages 0 and 1)
    load_stage(sb, soff, pAl, pAt, pB);
    pAl += BK; pAt += BK; pB += BK;
    load_stage(sb + STAGE_BYTES, soff, pAl, pAt, pB);
    pAl += BK; pAt += BK; pB += BK;

    float acc[4][8][4];
#pragma unroll
    for (int mt = 0; mt < 4; mt++)
#pragma unroll
        for (int nt = 0; nt < 8; nt++)
#pragma unroll
            for (int q = 0; q < 4; q++) acc[mt][nt][q] = 0.0f;

    // A ldsm lane map (standard): rows = lane&15, k-half = lane>>4
    const unsigned lrowA = lane & 15;
    const unsigned kbA4  = (lane >> 4) << 4;          // 0 or 16 bytes
    // B ldsm lane map giving ADJACENT register pairs per n8k16 fragment:
    //   matrices in order (n0-7,k0),(n0-7,k8),(n8-15,k0),(n8-15,k8)
    const unsigned lrowB = (lane & 7) + ((lane >> 4) << 3);
    const unsigned kbB4  = ((lane >> 3) & 1) << 4;    // 0 or 16 bytes
    // branch select: warp wn 0 -> A_light; wn 1 -> A_temp
    const unsigned aSel = wn ? (unsigned)STAGE_AL : 0u;

    // Hoisted swizzle decomposition:
    //   swz(r*128 + kb4 + kk*32) = r*128 + (kb4 ^ ((r&1)<<4)) + (kk*32 ^ (((r>>1)&3)<<5))
    unsigned cA[4], hA[4], cB[4], hB[4];
#pragma unroll
    for (int mt = 0; mt < 4; mt++) {
        unsigned r = wm * 64 + mt * 16 + lrowA;
        cA[mt] = aSel + r * 128 + (kbA4 ^ ((r & 1) << 4));
        hA[mt] = ((r >> 1) & 3) << 5;
    }
#pragma unroll
    for (int q = 0; q < 4; q++) {
        unsigned r = wn * 64 + q * 16 + lrowB;
        cB[q] = (unsigned)(STAGE_AL + STAGE_AT) + r * 128 + (kbB4 ^ ((r & 1) << 4));
        hB[q] = ((r >> 1) & 3) << 5;
    }

    for (int kt = 0; kt < NK; kt++) {
        asm volatile("cp.async.wait_group 1;" ::: "memory");
        __syncthreads();
        const unsigned st = sb + (kt & 1) * STAGE_BYTES;

#pragma unroll
        for (int kk = 0; kk < 4; kk++) {
            const unsigned K32 = (unsigned)(kk * 32);
            unsigned a[4][4], b[4][4];
#pragma unroll
            for (int mt = 0; mt < 4; mt++)
                ldsm_x4(a[mt][0], a[mt][1], a[mt][2], a[mt][3],
                        st + cA[mt] + (K32 ^ hA[mt]));
#pragma unroll
            for (int q = 0; q < 4; q++)
                ldsm_x4(b[q][0], b[q][1], b[q][2], b[q][3],
                        st + cB[q] + (K32 ^ hB[q]));
#pragma unroll
            for (int mt = 0; mt < 4; mt++)
#pragma unroll
                for (int nt = 0; nt < 8; nt++) {
                    const int g = nt >> 1, h = nt & 1;
                    // adjacent pair (2h, 2h+1): k0-15 of n-rows h*8..h*8+7
                    mma16816(acc[mt][nt][0], acc[mt][nt][1], acc[mt][nt][2], acc[mt][nt][3],
                             a[mt][0], a[mt][1], a[mt][2], a[mt][3],
                             b[g][2 * h], b[g][2 * h + 1]);
                }
        }
        __syncthreads();                  // all warps done reading stage kt&1
        if (kt + 2 < NK) {
            load_stage(sb + (kt & 1) * STAGE_BYTES, soff, pAl, pAt, pB);
            pAl += BK; pAt += BK; pB += BK;
        } else {
            asm volatile("cp.async.commit_group;" ::: "memory");  // uniform accounting
        }
    }

    // ---- fused epilogue: smem transpose then LSTM math ----
    float* sm = reinterpret_cast<float*>(smem);
    const int grp = lane >> 2;
    const int thr = lane & 3;
#pragma unroll
    for (int mt = 0; mt < 4; mt++) {
        const int r0 = wm * 64 + mt * 16 + grp;
#pragma unroll
        for (int nt = 0; nt < 8; nt++) {
            const int col = wn * 64 + nt * 8 + thr * 2;
            *reinterpret_cast<float2*>(&sm[(long)r0 * EPAD + col]) =
                make_float2(acc[mt][nt][0], acc[mt][nt][1]);
            *reinterpret_cast<float2*>(&sm[(long)(r0 + 8) * EPAD + col]) =
                make_float2(acc[mt][nt][2], acc[mt][nt][3]);
        }
    }
    __syncthreads();

    // read phase: thread -> (jj, mr); 16 passes over 128 rows (128 threads)
    const int jj = tid & 15;
    const int mr = tid >> 4;               // 0..7
    const int jg = j0 + jj;
    const float bf1 = __ldg(b0 + jg), bi1 = __ldg(b1 + jg);
    const float bc1 = __ldg(b2 + jg), bo1 = __ldg(b3 + jg);
    const float bf2 = __ldg(b4 + jg), bi2 = __ldg(b5 + jg);
    const float bc2 = __ldg(b6 + jg), bo2 = __ldg(b7 + jg);
#pragma unroll
    for (int pass = 0; pass < 16; pass++) {
        const int m  = pass * 8 + mr;
        const float* zr = &sm[(long)m * EPAD + jj];
        const float z0 = zr[0 * JT], z1 = zr[1 * JT], z2 = zr[2 * JT], z3 = zr[3 * JT];
        const float z4 = zr[4 * JT], z5 = zr[5 * JT], z6 = zr[6 * JT], z7 = zr[7 * JT];
        const long mg = m0 + m;
        const float c = __ldg(cl + mg * Hn + jg);

        const float f1 = sigf(z0 + bf1), i1 = sigf(z1 + bi1);
        const float ch1 = htanh(z2 + bc1), o1 = sigf(z3 + bo1);
        const float f2 = sigf(z4 + bf2), i2 = sigf(z5 + bi2);
        const float ch2 = htanh(z6 + bc2), o2 = sigf(z7 + bo2);

        const float cn = (f1 * c + i1 * ch1) + (f2 * c + i2 * ch2);
        const float hn = (o1 + o2) * htanh(cn);

        out[mg * Hn + jg] = hn;
        out[(long)Bn * Hn + mg * Hn + jg] = cn;
    }
}

// ---------------- launch ----------------
extern "C" void kernel_launch(void* const* d_in, const int* in_sizes, int n_in,
                              void* d_out, int out_size) {
    const float* y  = (const float*)d_in[0];
    const float* hl = (const float*)d_in[1];
    const float* cl = (const float*)d_in[2];
    const float* ht = (const float*)d_in[3];
    // d_in[4] = c_temp (unused by the reference math)
    const float* w0 = (const float*)d_in[5];
    const float* w1 = (const float*)d_in[7];
    const float* w2 = (const float*)d_in[9];
    const float* w3 = (const float*)d_in[11];
    const float* w4 = (const float*)d_in[13];
    const float* w5 = (const float*)d_in[15];
    const float* w6 = (const float*)d_in[17];
    const float* w7 = (const float*)d_in[19];
    const float* b0 = (const float*)d_in[6];
    const float* b1 = (const float*)d_in[8];
    const float* b2 = (const float*)d_in[10];
    const float* b3 = (const float*)d_in[12];
    const float* b4 = (const float*)d_in[14];
    const float* b5 = (const float*)d_in[16];
    const float* b6 = (const float*)d_in[18];
    const float* b7 = (const float*)d_in[20];
    float* out = (float*)d_out;

    cudaFuncSetAttribute(gemm_lstm, cudaFuncAttributeMaxDynamicSharedMemorySize, SMEM_TOTAL);

    convert_all<<<dim3(4096, 4), 192>>>(y, hl, ht, w0, w1, w2, w3, w4, w5, w6, w7);
    gemm_lstm<<<dim3(Nt / BN, Bn / BM), 128, SMEM_TOTAL>>>(
        cl, b0, b1, b2, b3, b4, b5, b6, b7, out);
}

// round 12
// speedup vs baseline: 1.0454x; 1.0454x over previous
#include <cuda_runtime.h>
#include <cuda_fp16.h>

#define DINL __device__ __forceinline__

// ---------------- problem constants ----------------
constexpr int Bn = 4096;
constexpr int In = 512;
constexpr int Hn = 1024;
constexpr int Kd = Hn + In;      // 1536
constexpr int Nt = 8 * Hn;       // 8192 packed gate columns

// ---------------- GEMM tiling ----------------
// Fused kernel, 2 CTAs/SM: BM=128 rows x BN=128 packed cols (16 j x 8 gate/branch).
// 8 warps (256 thr), warp tile 64x32: wm in {0,1}, wn in {0..3}.
// wn 0,1 -> A_light (cols 0..63 = gb 0..3), wn 2,3 -> A_temp (cols 64..127).
constexpr int BM = 128;
constexpr int BN = 128;
constexpr int JT = 16;                              // j-values per CTA
constexpr int BK = 64;                              // 128 bytes fp16 per row
constexpr int NK = Kd / BK;                         // 24
constexpr int STAGES = 2;
constexpr int STAGE_AL = BM * BK * 2;               // 16384
constexpr int STAGE_AT = BM * BK * 2;               // 16384
constexpr int STAGE_B  = BN * BK * 2;               // 16384
constexpr int STAGE_BYTES = STAGE_AL + STAGE_AT + STAGE_B;   // 49152
constexpr int SMEM_TOTAL = STAGES * STAGE_BYTES;    // 98304 per CTA (2 CTAs fit)
// epilogue transpose: 128 x 136 fp32 = 69632 B, reuses the same smem. fits.
constexpr int EPAD = 136;

// ---------------- scratch (device globals; no allocations) ----------------
__device__ __align__(1024) __half g_A[2][(long)Bn * Kd];          // 25 MB
__device__ __align__(1024) __half g_W[(long)Nt * Kd];             // 25 MB (packed)

// ---------------- PTX helpers (legal on plain sm_103 target) ----------
DINL unsigned cvta_smem(const void* p) {
    unsigned a;
    asm("{ .reg .u64 t; cvta.to.shared.u64 t, %1; cvt.u32.u64 %0, t; }" : "=r"(a) : "l"(p));
    return a;
}
DINL void cp_async16(unsigned dst, const void* src) {
    asm volatile("cp.async.cg.shared.global [%0], [%1], 16;" :: "r"(dst), "l"(src));
}
DINL void ldsm_x4(unsigned& r0, unsigned& r1, unsigned& r2, unsigned& r3, unsigned addr) {
    asm volatile("ldmatrix.sync.aligned.m8n8.x4.shared.b16 {%0,%1,%2,%3}, [%4];"
                 : "=r"(r0), "=r"(r1), "=r"(r2), "=r"(r3) : "r"(addr));
}
DINL void mma16816(float& d0, float& d1, float& d2, float& d3,
                   unsigned a0, unsigned a1, unsigned a2, unsigned a3,
                   unsigned b0, unsigned b1) {
    asm volatile(
        "mma.sync.aligned.m16n8k16.row.col.f32.f16.f16.f32 "
        "{%0,%1,%2,%3}, {%4,%5,%6,%7}, {%8,%9}, {%0,%1,%2,%3};"
        : "+f"(d0), "+f"(d1), "+f"(d2), "+f"(d3)
        : "r"(a0), "r"(a1), "r"(a2), "r"(a3), "r"(b0), "r"(b1));
}
DINL float htanh(float x) {
    float r;
    asm("tanh.approx.f32 %0, %1;" : "=f"(r) : "f"(x));
    return r;
}
DINL float sigf(float x) { return fmaf(htanh(x * 0.5f), 0.5f, 0.5f); }

// ---------------- convert kernel (one row per block, no div/mod) ----------
// grid (4096, 4), 192 threads. y=0/1: A branches. y=2/3: packed W rows
// n = (y-2)*4096 + x with jt=n>>7, gb=(n>>4)&7, jj=n&15, src row j=jt*16+jj.
__global__ void __launch_bounds__(192) convert_all(
        const float* __restrict__ y,
        const float* __restrict__ hl,
        const float* __restrict__ ht,
        const float* __restrict__ w0, const float* __restrict__ w1,
        const float* __restrict__ w2, const float* __restrict__ w3,
        const float* __restrict__ w4, const float* __restrict__ w5,
        const float* __restrict__ w6, const float* __restrict__ w7) {
    const int t  = threadIdx.x;
    const int bx = blockIdx.x;
    const int by = blockIdx.y;
    const float* src;
    __half* dst;
    if (by < 2) {
        const float* hsrc = by ? ht : hl;
        src = (t < 128) ? hsrc + (long)bx * Hn + t * 8
                        : y + (long)bx * In + (t - 128) * 8;
        dst = &g_A[by][(long)bx * Kd + t * 8];
    } else {
        const int n  = (by - 2) * 4096 + bx;
        const int jt = n >> 7;
        const int gb = (n >> 4) & 7;
        const int jj = n & 15;
        const int j  = jt * JT + jj;
        const float* wp = (gb == 0) ? w0 : (gb == 1) ? w1 : (gb == 2) ? w2 : (gb == 3) ? w3
                        : (gb == 4) ? w4 : (gb == 5) ? w5 : (gb == 6) ? w6 : w7;
        src = wp + (long)j * Kd + t * 8;
        dst = &g_W[(long)n * Kd + t * 8];
    }
    float4 a = reinterpret_cast<const float4*>(src)[0];
    float4 b = reinterpret_cast<const float4*>(src)[1];
    __half2 h0 = __floats2half2_rn(a.x, a.y);
    __half2 h1 = __floats2half2_rn(a.z, a.w);
    __half2 h2 = __floats2half2_rn(b.x, b.y);
    __half2 h3 = __floats2half2_rn(b.z, b.w);
    uint4 v = make_uint4(*(unsigned*)&h0, *(unsigned*)&h1,
                         *(unsigned*)&h2, *(unsigned*)&h3);
    *reinterpret_cast<uint4*>(dst) = v;
}

// ---------------- fused GEMM + LSTM kernel ----------------
// 48KB stage: A_l (128x128B) + A_t + B, 256 threads, 4 iters of 32 rows each.
DINL void load_stage(unsigned sbase, unsigned soff,
                     const __half* pAl, const __half* pAt, const __half* pB) {
#pragma unroll
    for (int i = 0; i < 4; i++)
        cp_async16(sbase + i * 4096 + soff, pAl + (long)i * 32 * Kd);
#pragma unroll
    for (int i = 0; i < 4; i++)
        cp_async16(sbase + STAGE_AL + i * 4096 + soff, pAt + (long)i * 32 * Kd);
#pragma unroll
    for (int i = 0; i < 4; i++)
        cp_async16(sbase + STAGE_AL + STAGE_AT + i * 4096 + soff, pB + (long)i * 32 * Kd);
    asm volatile("cp.async.commit_group;" ::: "memory");
}

__global__ void __launch_bounds__(256, 2) gemm_lstm(
        const float* __restrict__ cl,
        const float* __restrict__ b0, const float* __restrict__ b1,
        const float* __restrict__ b2, const float* __restrict__ b3,
        const float* __restrict__ b4, const float* __restrict__ b5,
        const float* __restrict__ b6, const float* __restrict__ b7,
        float* __restrict__ out) {
    extern __shared__ char smem[];
    const unsigned tid  = threadIdx.x;
    const unsigned wid  = tid >> 5;
    const unsigned lane = tid & 31;
    const unsigned sb   = cvta_smem(smem);
    const unsigned wm   = wid & 1;        // 2 warps along M -> 64 rows each
    const unsigned wn   = wid >> 1;       // 4 warps along N -> 32 cols each
    const int n0 = blockIdx.x * BN;       // packed col base
    const int m0 = blockIdx.y * BM;
    const int j0 = blockIdx.x * JT;

    // per-thread cp.async bases (affine; swizzle term constant since 32 % 8 == 0)
    const unsigned trow = tid >> 3;                 // 0..31
    const unsigned tcol = tid & 7;
    const __half* pAl = g_A[0] + (long)(m0 + trow) * Kd + tcol * 8;
    const __half* pAt = g_A[1] + (long)(m0 + trow) * Kd + tcol * 8;
    const __half* pB  = g_W   + (long)(n0 + trow) * Kd + tcol * 8;
    const unsigned soff = trow * 128 + ((tcol * 16) ^ ((trow & 7) << 4));

    // prologue loads (stages 0 and 1)
    load_stage(sb, soff, pAl, pAt, pB);
    pAl += BK; pAt += BK; pB += BK;
    load_stage(sb + STAGE_BYTES, soff, pAl, pAt, pB);
    pAl += BK; pAt += BK; pB += BK;

    float acc[4][4][4];
#pragma unroll
    for (int mt = 0; mt < 4; mt++)
#pragma unroll
        for (int nt = 0; nt < 4; nt++)
#pragma unroll
            for (int q = 0; q < 4; q++) acc[mt][nt][q] = 0.0f;

    // A ldsm lane map (standard): rows = lane&15, k-half = lane>>4
    const unsigned lrowA = lane & 15;
    const unsigned kbA4  = (lane >> 4) << 4;          // 0 or 16 bytes
    // B ldsm lane map giving ADJACENT register pairs per n8k16 fragment:
    //   matrices in order (n0-7,k0),(n0-7,k8),(n8-15,k0),(n8-15,k8)
    const unsigned lrowB = (lane & 7) + ((lane >> 4) << 3);
    const unsigned kbB4  = ((lane >> 3) & 1) << 4;    // 0 or 16 bytes
    // branch select: warps wn 0,1 -> A_light; wn 2,3 -> A_temp
    const unsigned aSel = (wn >> 1) ? (unsigned)STAGE_AL : 0u;

    // Hoisted swizzle decomposition:
    //   swz(r*128 + kb4 + kk*32) = r*128 + (kb4 ^ ((r&1)<<4)) + (kk*32 ^ (((r>>1)&3)<<5))
    unsigned cA[4], hA[4], cB[2], hB[2];
#pragma unroll
    for (int mt = 0; mt < 4; mt++) {
        unsigned r = wm * 64 + mt * 16 + lrowA;
        cA[mt] = aSel + r * 128 + (kbA4 ^ ((r & 1) << 4));
        hA[mt] = ((r >> 1) & 3) << 5;
    }
#pragma unroll
    for (int q = 0; q < 2; q++) {
        unsigned r = wn * 32 + q * 16 + lrowB;
        cB[q] = (unsigned)(STAGE_AL + STAGE_AT) + r * 128 + (kbB4 ^ ((r & 1) << 4));
        hB[q] = ((r >> 1) & 3) << 5;
    }

    for (int kt = 0; kt < NK; kt++) {
        asm volatile("cp.async.wait_group 1;" ::: "memory");
        __syncthreads();
        const unsigned st = sb + (kt & 1) * STAGE_BYTES;

#pragma unroll
        for (int kk = 0; kk < 4; kk++) {
            const unsigned K32 = (unsigned)(kk * 32);
            unsigned a[4][4], b[2][4];
#pragma unroll
            for (int mt = 0; mt < 4; mt++)
                ldsm_x4(a[mt][0], a[mt][1], a[mt][2], a[mt][3],
                        st + cA[mt] + (K32 ^ hA[mt]));
#pragma unroll
            for (int q = 0; q < 2; q++)
                ldsm_x4(b[q][0], b[q][1], b[q][2], b[q][3],
                        st + cB[q] + (K32 ^ hB[q]));

            if (kk == 3) {
                // All smem reads of stage kt&1 complete (fragments in regs).
                // Reload this stage for tile kt+2, overlapped with kk=3 MMAs.
                __syncthreads();
                if (kt + 2 < NK) {
                    load_stage(sb + (kt & 1) * STAGE_BYTES, soff, pAl, pAt, pB);
                    pAl += BK; pAt += BK; pB += BK;
                } else {
                    asm volatile("cp.async.commit_group;" ::: "memory");  // uniform accounting
                }
            }

#pragma unroll
            for (int mt = 0; mt < 4; mt++)
#pragma unroll
                for (int nt = 0; nt < 4; nt++) {
                    const int g = nt >> 1, h = nt & 1;
                    // adjacent pair (2h, 2h+1): k0-15 of n-rows h*8..h*8+7
                    mma16816(acc[mt][nt][0], acc[mt][nt][1], acc[mt][nt][2], acc[mt][nt][3],
                             a[mt][0], a[mt][1], a[mt][2], a[mt][3],
                             b[g][2 * h], b[g][2 * h + 1]);
                }
        }
    }

    // ---- fused epilogue: smem transpose then LSTM math ----
    __syncthreads();                       // stage buffers no longer needed
    float* sm = reinterpret_cast<float*>(smem);
    const int grp = lane >> 2;
    const int thr = lane & 3;
#pragma unroll
    for (int mt = 0; mt < 4; mt++) {
        const int r0 = wm * 64 + mt * 16 + grp;
#pragma unroll
        for (int nt = 0; nt < 4; nt++) {
            const int col = wn * 32 + nt * 8 + thr * 2;
            *reinterpret_cast<float2*>(&sm[(long)r0 * EPAD + col]) =
                make_float2(acc[mt][nt][0], acc[mt][nt][1]);
            *reinterpret_cast<float2*>(&sm[(long)(r0 + 8) * EPAD + col]) =
                make_float2(acc[mt][nt][2], acc[mt][nt][3]);
        }
    }
    __syncthreads();

    // read phase: thread -> (jj, mr); 8 passes over 128 rows
    const int jj = tid & 15;
    const int mr = tid >> 4;               // 0..15
    const int jg = j0 + jj;
    const float bf1 = __ldg(b0 + jg), bi1 = __ldg(b1 + jg);
    const float bc1 = __ldg(b2 + jg), bo1 = __ldg(b3 + jg);
    const float bf2 = __ldg(b4 + jg), bi2 = __ldg(b5 + jg);
    const float bc2 = __ldg(b6 + jg), bo2 = __ldg(b7 + jg);
#pragma unroll
    for (int pass = 0; pass < 8; pass++) {
        const int m  = pass * 16 + mr;
        const float* zr = &sm[(long)m * EPAD + jj];
        const float z0 = zr[0 * JT], z1 = zr[1 * JT], z2 = zr[2 * JT], z3 = zr[3 * JT];
        const float z4 = zr[4 * JT], z5 = zr[5 * JT], z6 = zr[6 * JT], z7 = zr[7 * JT];
        const long mg = m0 + m;
        const float c = __ldg(cl + mg * Hn + jg);

        const float f1 = sigf(z0 + bf1), i1 = sigf(z1 + bi1);
        const float ch1 = htanh(z2 + bc1), o1 = sigf(z3 + bo1);
        const float f2 = sigf(z4 + bf2), i2 = sigf(z5 + bi2);
        const float ch2 = htanh(z6 + bc2), o2 = sigf(z7 + bo2);

        const float cn = (f1 * c + i1 * ch1) + (f2 * c + i2 * ch2);
        const float hn = (o1 + o2) * htanh(cn);

        out[mg * Hn + jg] = hn;
        out[(long)Bn * Hn + mg * Hn + jg] = cn;
    }
}

// ---------------- launch ----------------
extern "C" void kernel_launch(void* const* d_in, const int* in_sizes, int n_in,
                              void* d_out, int out_size) {
    const float* y  = (const float*)d_in[0];
    const float* hl = (const float*)d_in[1];
    const float* cl = (const float*)d_in[2];
    const float* ht = (const float*)d_in[3];
    // d_in[4] = c_temp (unused by the reference math)
    const float* w0 = (const float*)d_in[5];
    const float* w1 = (const float*)d_in[7];
    const float* w2 = (const float*)d_in[9];
    const float* w3 = (const float*)d_in[11];
    const float* w4 = (const float*)d_in[13];
    const float* w5 = (const float*)d_in[15];
    const float* w6 = (const float*)d_in[17];
    const float* w7 = (const float*)d_in[19];
    const float* b0 = (const float*)d_in[6];
    const float* b1 = (const float*)d_in[8];
    const float* b2 = (const float*)d_in[10];
    const float* b3 = (const float*)d_in[12];
    const float* b4 = (const float*)d_in[14];
    const float* b5 = (const float*)d_in[16];
    const float* b6 = (const float*)d_in[18];
    const float* b7 = (const float*)d_in[20];
    float* out = (float*)d_out;

    cudaFuncSetAttribute(gemm_lstm, cudaFuncAttributeMaxDynamicSharedMemorySize, SMEM_TOTAL);

    convert_all<<<dim3(4096, 4), 192>>>(y, hl, ht, w0, w1, w2, w3, w4, w5, w6, w7);
    gemm_lstm<<<dim3(Nt / BN, Bn / BM), 256, SMEM_TOTAL>>>(
        cl, b0, b1, b2, b3, b4, b5, b6, b7, out);
}